// round 16
// baseline (speedup 1.0000x reference)
#include <cuda_runtime.h>
#include <math.h>

#define B_    4
#define N_    8000
#define FIN   256
#define DD    128
#define DFF   128
#define NBINS 16
#define BINSZ 500
#define KNN   8
#define E_TOT (B_*N_*KNN)     /* 256000 */
#define ROTC  100             /* MAX_NUM_BINS/2, row stride of rot */

// ---------------- scratch (static device globals; no allocation) -------------
__device__ float g_pe[B_*N_*DD];          // encoded points
__device__ float g_norm[B_*N_];           // squared norms of encoded points
__device__ int   g_bin[B_*N_];            // LSH bin per point
__device__ int   g_perm[B_*N_];           // stable argsort by bin == bins_split
__device__ int   g_dst[E_TOT];            // per (b,src,slot) dst, dst-sorted
__device__ float g_val[E_TOT];            // matching kernel values
__device__ float g_h12[(size_t)B_*N_*256];// [point][0:128]=X*W1a, [128:256]=X*W1b

// ---------------- packed f32x2 helpers ---------------------------------------
#define FMA2(d, a, b) asm("fma.rn.f32x2 %0, %1, %2, %0;" : "+l"(d) : "l"(a), "l"(b))

__device__ __forceinline__ unsigned long long dup2(float v) {
    unsigned iv = __float_as_uint(v);
    unsigned long long r;
    asm("mov.b64 %0, {%1, %1};" : "=l"(r) : "r"(iv), "r"(iv));
    return r;
}
__device__ __forceinline__ float f2lo(unsigned long long u) {
    return __uint_as_float((unsigned)u);
}
__device__ __forceinline__ float f2hi(unsigned long long u) {
    return __uint_as_float((unsigned)(u >> 32));
}

// ---------------- cp.async helpers --------------------------------------------
#define CPA16(dst, src) asm volatile( \
    "cp.async.ca.shared.global [%0], [%1], 16;" :: "r"(dst), "l"(src))
#define CPA4(dst, src) asm volatile( \
    "cp.async.ca.shared.global [%0], [%1], 4;" :: "r"(dst), "l"(src))
#define CPACOMMIT() asm volatile("cp.async.commit_group;")
#define CPAWAIT0()  asm volatile("cp.async.wait_group 0;")

// +inf-keyed sentinel: sorts above every finite-d2 key; threshold bootstraps
// to +inf so the first KNN candidates always pass.
#define KEY_INIT 0x7F800000FFFFFFFFull

// ---------------- kernel 1: tiled encoder FFN + norms + LSH bin --------------
#define ENC_PTS 64
__global__ __launch_bounds__(256) void enc_kernel(
        const float* __restrict__ inputs,
        const float* __restrict__ w1, const float* __restrict__ b1,
        const float* __restrict__ w2, const float* __restrict__ b2,
        const float* __restrict__ rot) {
    extern __shared__ float sm[];
    float* xs = sm;                 // [64][64]
    float* ws = sm + 4096;          // [64][128]
    float* hs = sm + 12288;         // [64][128]
    __shared__ float b1s[DFF], b2s[DD];
    __shared__ float rots[DD * 8];
    __shared__ float ms[ENC_PTS][8];
    int tid = threadIdx.x;
    int wid = tid >> 5, tx = tid & 31;
    int n0 = blockIdx.x * ENC_PTS;

    if (tid < DFF) b1s[tid] = b1[tid];
    else b2s[tid - DFF] = b2[tid - DFF];
    for (int t = tid; t < DD * 8; t += 256) {
        int d = t >> 3, j = t & 7;
        rots[t] = rot[d * ROTC + j];
    }

    unsigned long long acc[8][2];
    #pragma unroll
    for (int rr = 0; rr < 8; ++rr) { acc[rr][0] = 0ull; acc[rr][1] = 0ull; }

    for (int kc = 0; kc < FIN; kc += 64) {
        __syncthreads();
        for (int t = tid; t < 1024; t += 256) {
            int p = t >> 4, k4 = t & 15;
            ((float4*)xs)[p * 16 + k4] =
                ((const float4*)(inputs + (size_t)(n0 + p) * FIN + kc))[k4];
        }
        for (int t = tid; t < 2048; t += 256) {
            int k = t >> 5, c4 = t & 31;
            ((float4*)ws)[k * 32 + c4] =
                ((const float4*)(w1 + (size_t)(kc + k) * DFF))[c4];
        }
        __syncthreads();
        for (int k4 = 0; k4 < 64; k4 += 4) {
            float4 e4[8];
            #pragma unroll
            for (int rr = 0; rr < 8; ++rr)
                e4[rr] = *(const float4*)&xs[(wid * 8 + rr) * 64 + k4];
            #pragma unroll
            for (int j = 0; j < 4; ++j) {
                ulonglong2 wp = *(const ulonglong2*)&ws[(k4 + j) * DFF + tx * 4];
                #pragma unroll
                for (int rr = 0; rr < 8; ++rr) {
                    float ev = (j == 0) ? e4[rr].x : (j == 1) ? e4[rr].y
                             : (j == 2) ? e4[rr].z : e4[rr].w;
                    unsigned long long ed = dup2(ev);
                    FMA2(acc[rr][0], ed, wp.x);
                    FMA2(acc[rr][1], ed, wp.y);
                }
            }
        }
    }
    #pragma unroll
    for (int rr = 0; rr < 8; ++rr) {
        int p = wid * 8 + rr;
        float h0 = f2lo(acc[rr][0]) + b1s[tx * 4 + 0];
        float h1 = f2hi(acc[rr][0]) + b1s[tx * 4 + 1];
        float h2 = f2lo(acc[rr][1]) + b1s[tx * 4 + 2];
        float h3 = f2hi(acc[rr][1]) + b1s[tx * 4 + 3];
        h0 = h0 > 0.f ? h0 : expm1f(h0);
        h1 = h1 > 0.f ? h1 : expm1f(h1);
        h2 = h2 > 0.f ? h2 : expm1f(h2);
        h3 = h3 > 0.f ? h3 : expm1f(h3);
        *(float4*)&hs[p * DFF + tx * 4] = make_float4(h0, h1, h2, h3);
    }

    #pragma unroll
    for (int rr = 0; rr < 8; ++rr) { acc[rr][0] = 0ull; acc[rr][1] = 0ull; }
    for (int half = 0; half < 2; ++half) {
        __syncthreads();
        for (int t = tid; t < 2048; t += 256) {
            int k = t >> 5, c4 = t & 31;
            ((float4*)ws)[k * 32 + c4] =
                ((const float4*)(w2 + (size_t)(half * 64 + k) * DD))[c4];
        }
        __syncthreads();
        for (int k4 = 0; k4 < 64; k4 += 4) {
            float4 e4[8];
            #pragma unroll
            for (int rr = 0; rr < 8; ++rr)
                e4[rr] = *(const float4*)&hs[(wid * 8 + rr) * DFF + half * 64 + k4];
            #pragma unroll
            for (int j = 0; j < 4; ++j) {
                ulonglong2 wp = *(const ulonglong2*)&ws[(k4 + j) * DD + tx * 4];
                #pragma unroll
                for (int rr = 0; rr < 8; ++rr) {
                    float ev = (j == 0) ? e4[rr].x : (j == 1) ? e4[rr].y
                             : (j == 2) ? e4[rr].z : e4[rr].w;
                    unsigned long long ed = dup2(ev);
                    FMA2(acc[rr][0], ed, wp.x);
                    FMA2(acc[rr][1], ed, wp.y);
                }
            }
        }
    }
    __syncthreads();
    #pragma unroll
    for (int rr = 0; rr < 8; ++rr) {
        int p = wid * 8 + rr;
        int n = n0 + p;
        float o0 = f2lo(acc[rr][0]) + b2s[tx * 4 + 0];
        float o1 = f2hi(acc[rr][0]) + b2s[tx * 4 + 1];
        float o2 = f2lo(acc[rr][1]) + b2s[tx * 4 + 2];
        float o3 = f2hi(acc[rr][1]) + b2s[tx * 4 + 3];
        float4 ov = make_float4(o0, o1, o2, o3);
        *(float4*)&hs[p * DD + tx * 4] = ov;
        *(float4*)&g_pe[(size_t)n * DD + tx * 4] = ov;
        float pn = o0 * o0 + o1 * o1 + o2 * o2 + o3 * o3;
        #pragma unroll
        for (int off = 16; off; off >>= 1)
            pn += __shfl_xor_sync(0xffffffffu, pn, off);
        if (tx == 0) g_norm[n] = pn;
    }
    __syncthreads();

    for (int t = tid; t < ENC_PTS * 8; t += 256) {
        int p = t >> 3, j = t & 7;
        float m = 0.f;
        #pragma unroll 8
        for (int d = 0; d < DD; ++d) m += hs[p * DD + d] * rots[d * 8 + j];
        ms[p][j] = m;
    }
    __syncthreads();
    if (tid < ENC_PTS) {
        float best = ms[tid][0]; int bi = 0;
        #pragma unroll
        for (int j = 1; j < NBINS; ++j) {
            float v = (j < 8) ? ms[tid][j] : -ms[tid][j - 8];
            if (v > best) { best = v; bi = j; }
        }
        g_bin[n0 + tid] = bi;
    }
}

// ---------------- kernel 1b: H12 = X @ [W1a | W1b] (edge-FFN precompute) -----
__global__ __launch_bounds__(512) void h12_kernel(
        const float* __restrict__ inputs, const float* __restrict__ ew1) {
    extern __shared__ float sm[];
    float* xs = sm;                 // [128][64]
    float* ws = sm + 8192;          // [64][256]
    int tid = threadIdx.x;
    int wid = tid >> 5, tx = tid & 31;
    int n0 = blockIdx.x * 128;

    unsigned long long acc[8][4];
    #pragma unroll
    for (int rr = 0; rr < 8; ++rr)
        acc[rr][0] = acc[rr][1] = acc[rr][2] = acc[rr][3] = 0ull;

    for (int kc = 0; kc < FIN; kc += 64) {
        __syncthreads();
        for (int t = tid; t < 2048; t += 512) {
            int p = t >> 4, k4 = t & 15;
            ((float4*)xs)[p * 16 + k4] =
                ((const float4*)(inputs + (size_t)(n0 + p) * FIN + kc))[k4];
        }
        for (int t = tid; t < 4096; t += 512) {
            int k = t >> 6, j4 = t & 63;
            const float* srcp = (j4 < 32)
                ? (ew1 + (size_t)(kc + k) * DFF + j4 * 4)
                : (ew1 + (size_t)(256 + kc + k) * DFF + (j4 - 32) * 4);
            ((float4*)ws)[k * 64 + j4] = *(const float4*)srcp;
        }
        __syncthreads();
        for (int k4 = 0; k4 < 64; k4 += 4) {
            float4 e4[8];
            #pragma unroll
            for (int rr = 0; rr < 8; ++rr)
                e4[rr] = *(const float4*)&xs[(wid * 8 + rr) * 64 + k4];
            #pragma unroll
            for (int j = 0; j < 4; ++j) {
                ulonglong2 wa = *(const ulonglong2*)&ws[(k4 + j) * 256 + tx * 4];
                ulonglong2 wb = *(const ulonglong2*)&ws[(k4 + j) * 256 + 128 + tx * 4];
                #pragma unroll
                for (int rr = 0; rr < 8; ++rr) {
                    float ev = (j == 0) ? e4[rr].x : (j == 1) ? e4[rr].y
                             : (j == 2) ? e4[rr].z : e4[rr].w;
                    unsigned long long ed = dup2(ev);
                    FMA2(acc[rr][0], ed, wa.x);
                    FMA2(acc[rr][1], ed, wa.y);
                    FMA2(acc[rr][2], ed, wb.x);
                    FMA2(acc[rr][3], ed, wb.y);
                }
            }
        }
    }
    #pragma unroll
    for (int rr = 0; rr < 8; ++rr) {
        size_t n = (size_t)(n0 + wid * 8 + rr);
        *(float4*)&g_h12[n * 256 + tx * 4] =
            make_float4(f2lo(acc[rr][0]), f2hi(acc[rr][0]),
                        f2lo(acc[rr][1]), f2hi(acc[rr][1]));
        *(float4*)&g_h12[n * 256 + 128 + tx * 4] =
            make_float4(f2lo(acc[rr][2]), f2hi(acc[rr][2]),
                        f2lo(acc[rr][3]), f2hi(acc[rr][3]));
    }
}

// ---------------- kernel 2: stable counting sort, 1024 threads ---------------
__global__ __launch_bounds__(1024) void sort_kernel(float* __restrict__ out,
                                                    int out_size) {
    int b = blockIdx.x;
    __shared__ int bins[N_];
    __shared__ int cnt[NBINS];
    __shared__ int basebin[NBINS];
    __shared__ int wcnt[32][NBINS];
    int tid = threadIdx.x, wid = tid >> 5, lane = tid & 31;
    unsigned ltmask = (1u << lane) - 1u;
    for (int i = tid; i < N_; i += 1024) bins[i] = g_bin[b*N_ + i];
    if (tid < NBINS) cnt[tid] = 0;
    __syncthreads();
    for (int i = tid; i < N_; i += 1024) {
        int bi = bins[i];
        unsigned m = __match_any_sync(0xffffffffu, bi);
        if ((m & ltmask) == 0) atomicAdd(&cnt[bi], __popc(m));
    }
    __syncthreads();
    if (tid == 0) {
        int s = 0;
        for (int k = 0; k < NBINS; ++k) { basebin[k] = s; s += cnt[k]; }
    }
    __syncthreads();
    for (int c0 = 0; c0 < N_; c0 += 1024) {
        int i = c0 + tid;
        int bi = (i < N_) ? bins[i] : -1;
        unsigned m = __match_any_sync(0xffffffffu, bi);
        int wrank = __popc(m & ltmask);
        if (tid < 512) wcnt[tid >> 4][tid & 15] = 0;
        __syncthreads();
        if ((m & ltmask) == 0 && bi >= 0) wcnt[wid][bi] = __popc(m);
        __syncthreads();
        if (bi >= 0) {
            int off = basebin[bi];
            for (int w = 0; w < wid; ++w) off += wcnt[w][bi];
            g_perm[b*N_ + off + wrank] = i;
        }
        __syncthreads();
        if (tid < NBINS) {
            int t = 0;
            #pragma unroll
            for (int w = 0; w < 32; ++w) t += wcnt[w][tid];
            basebin[tid] += t;
        }
        __syncthreads();
    }
    for (int i = tid; i < N_; i += 1024) {
        int idx = 4*E_TOT + b*N_ + i;
        if (idx < out_size) out[idx] = (float)g_perm[b*N_ + i];
    }
}

// ---------------- kernel 3: top-8 by min d2, load-balanced --------------------
// 192 CTAs x 512 threads (1/SM): 64 (b,bin) x segments (216, 216, 68); big
// segments first so the 44 leftover smalls backfill freed SMs. 64 groups of
// 8 lanes, 4 rows/group (256-row capacity). 4 cols/iter; 4-col transposed
// butterfly reduce; thresholds in registers; inserts into smem u64 keys.
#define TKC 64
__global__ __launch_bounds__(512, 1) void topk_kernel() {
    int bid = blockIdx.x;
    int bbin, rbase, rcount;
    if (bid < 128) { bbin = bid >> 1; rbase = (bid & 1) * 216; rcount = 216; }
    else           { bbin = bid - 128; rbase = 432; rcount = BINSZ - 432; }
    int b = bbin / NBINS, bin = bbin % NBINS;

    extern __shared__ float smx[];
    float4* colbuf4 = (float4*)smx;                        // [2][64][32] f4 64KB
    float* cns = smx + 2 * TKC * 128;                      // [2][64]
    unsigned long long* keys =
        (unsigned long long*)(smx + 2 * TKC * 128 + 2 * TKC);  // [256][8] 16KB
    unsigned smem_u = (unsigned)__cvta_generic_to_shared(smx);
    unsigned cb_u   = smem_u;
    unsigned cn_u   = smem_u + 2 * TKC * 128 * 4;

    const int* perm = g_perm + b*N_ + bin*BINSZ;
    const float* pe = g_pe + (size_t)b*N_*DD;
    const float* nrm = g_norm + b*N_;
    int tid = threadIdx.x;
    int grp = tid >> 3, l8 = tid & 7;                      // 64 groups x 8 lanes

    unsigned rvm = 0;
    float rn[4];
    ulonglong2 rp[4][4];                                   // 4 rows x 16 floats
    #pragma unroll
    for (int r = 0; r < 4; ++r) {
        int lr = grp + 64*r;
        int row = rbase + lr;
        if (lr < rcount) rvm |= 1u << r;
        int rowc = (lr < rcount) ? row : rbase;
        int rs = perm[rowc];
        rn[r] = nrm[rs];
        const ulonglong2* prow = (const ulonglong2*)(pe + (size_t)rs*DD);
        #pragma unroll
        for (int ch = 0; ch < 4; ++ch) rp[r][ch] = prow[l8 + 8*ch];
    }
    for (int t = tid; t < 256*8; t += 512) keys[t] = KEY_INIT;
    float thr[4];
    #pragma unroll
    for (int r = 0; r < 4; ++r) thr[r] = __uint_as_float(0x7F800000u); // +inf

    const int NT = (BINSZ + TKC - 1) / TKC;                // 8 tiles
    {
        for (int t = tid; t < TKC*32; t += 512) {
            int c = t >> 5, k = t & 31;
            CPA16(cb_u + (unsigned)t * 16,
                  (const void*)(pe + (size_t)perm[c]*DD + k*4));
        }
        if (tid < TKC) CPA4(cn_u + tid*4, (const void*)(nrm + perm[tid]));
        CPACOMMIT();
    }
    CPAWAIT0();
    __syncthreads();

    int lc = l8 & 3;                                       // lane's col slot
    for (int tIdx = 0; tIdx < NT; ++tIdx) {
        int bf = tIdx & 1;
        int cc = tIdx * TKC;
        int csize = min(TKC, BINSZ - cc);                  // 64 or 52 (div by 4)
        if (tIdx + 1 < NT) {
            int ncc = cc + TKC;
            int ncs = min(TKC, BINSZ - ncc);
            unsigned cbn = cb_u + (unsigned)(bf ^ 1) * TKC * 128 * 4;
            for (int t = tid; t < ncs*32; t += 512) {
                int c = t >> 5, k = t & 31;
                CPA16(cbn + (unsigned)t * 16,
                      (const void*)(pe + (size_t)perm[ncc + c]*DD + k*4));
            }
            if (tid < ncs) CPA4(cn_u + ((bf ^ 1) * TKC + tid) * 4,
                                (const void*)(nrm + perm[ncc + tid]));
            CPACOMMIT();
        }
        const float4* cb = colbuf4 + bf * TKC * 32;
        const float* cnorm = cns + bf * TKC;
        for (int c = 0; c < csize; c += 4) {
            unsigned long long acc[4][4];                  // [row][col]
            #pragma unroll
            for (int r = 0; r < 4; ++r)
                #pragma unroll
                for (int j = 0; j < 4; ++j) acc[r][j] = 0ull;
            const ulonglong2* col0 = (const ulonglong2*)&cb[(c+0)*32];
            const ulonglong2* col1 = (const ulonglong2*)&cb[(c+1)*32];
            const ulonglong2* col2 = (const ulonglong2*)&cb[(c+2)*32];
            const ulonglong2* col3 = (const ulonglong2*)&cb[(c+3)*32];
            #pragma unroll
            for (int ch = 0; ch < 4; ++ch) {
                ulonglong2 cv0 = col0[l8 + 8*ch];
                ulonglong2 cv1 = col1[l8 + 8*ch];
                ulonglong2 cv2 = col2[l8 + 8*ch];
                ulonglong2 cv3 = col3[l8 + 8*ch];
                #pragma unroll
                for (int r = 0; r < 4; ++r) {
                    FMA2(acc[r][0], rp[r][ch].x, cv0.x);
                    FMA2(acc[r][0], rp[r][ch].y, cv0.y);
                    FMA2(acc[r][1], rp[r][ch].x, cv1.x);
                    FMA2(acc[r][1], rp[r][ch].y, cv1.y);
                    FMA2(acc[r][2], rp[r][ch].x, cv2.x);
                    FMA2(acc[r][2], rp[r][ch].y, cv2.y);
                    FMA2(acc[r][3], rp[r][ch].x, cv3.x);
                    FMA2(acc[r][3], rp[r][ch].y, cv3.y);
                }
            }
            float cn = cnorm[c + lc];
            float d2v[4];
            unsigned passm = 0;
            #pragma unroll
            for (int r = 0; r < 4; ++r) {
                float p0 = f2lo(acc[r][0]) + f2hi(acc[r][0]);
                float p1 = f2lo(acc[r][1]) + f2hi(acc[r][1]);
                float p2 = f2lo(acc[r][2]) + f2hi(acc[r][2]);
                float p3 = f2lo(acc[r][3]) + f2hi(acc[r][3]);
                float vA = (l8 & 1) ? p0 : p1;
                float qA = __shfl_xor_sync(0xffffffffu, vA, 1, 8);
                float s01 = ((l8 & 1) ? p1 : p0) + qA;
                float vB = (l8 & 1) ? p2 : p3;
                float qB = __shfl_xor_sync(0xffffffffu, vB, 1, 8);
                float s23 = ((l8 & 1) ? p3 : p2) + qB;
                float vC = (l8 & 2) ? s01 : s23;
                float qC = __shfl_xor_sync(0xffffffffu, vC, 2, 8);
                float a = ((l8 & 2) ? s23 : s01) + qC;
                a += __shfl_xor_sync(0xffffffffu, a, 4, 8);
                float d2 = fmaxf((rn[r] - 2.0f * a) + cn, 1e-6f);
                d2v[r] = d2;
                if (((rvm >> r) & 1u) && l8 < 4 && d2 <= thr[r])
                    passm |= 1u << r;
            }
            if (__ballot_sync(0xffffffffu, passm)) {
                #pragma unroll
                for (int t = 0; t < 4; ++t) {
                    if (l8 == t && passm) {
                        #pragma unroll
                        for (int r = 0; r < 4; ++r) {
                            if ((passm >> r) & 1u) {
                                unsigned long long* kr = &keys[(r*64 + grp)*8];
                                unsigned long long key =
                                    ((unsigned long long)
                                     __float_as_uint(d2v[r]) << 32)
                                    | (unsigned)(cc + c + t);
                                if (key < kr[7]) {
                                    kr[7] = key;
                                    #pragma unroll
                                    for (int s = 7; s > 0; --s) {
                                        if (kr[s] < kr[s-1]) {
                                            unsigned long long tm = kr[s];
                                            kr[s] = kr[s-1]; kr[s-1] = tm;
                                        } else break;
                                    }
                                }
                            }
                        }
                    }
                    __syncwarp();
                }
                #pragma unroll
                for (int r = 0; r < 4; ++r)
                    thr[r] = __uint_as_float(
                        (unsigned)(keys[(r*64 + grp)*8 + 7] >> 32));
            }
        }
        CPAWAIT0();
        __syncthreads();
    }
    // ---- writeback: one thread per local row ----
    if (tid < 256 && tid < rcount) {
        int grow = rbase + tid;
        int rsrc = perm[grow];
        unsigned long long* kr = &keys[tid * 8];
        int dsts[KNN]; float vals[KNN];
        #pragma unroll
        for (int s = 0; s < KNN; ++s) {
            unsigned long long k = kr[s];
            float d2 = __uint_as_float((unsigned)(k >> 32));
            dsts[s] = perm[(unsigned)k];
            vals[s] = expf(-0.1f * sqrtf(d2));
        }
        #pragma unroll
        for (int i = 1; i < KNN; ++i) {
            int dk = dsts[i]; float vk = vals[i]; int j = i - 1;
            while (j >= 0 && dsts[j] > dk) {
                dsts[j+1] = dsts[j]; vals[j+1] = vals[j]; --j;
            }
            dsts[j+1] = dk; vals[j+1] = vk;
        }
        size_t base = ((size_t)b*N_ + rsrc) * KNN;
        #pragma unroll
        for (int s = 0; s < KNN; ++s) {
            g_dst[base+s] = dsts[s]; g_val[base+s] = vals[s];
        }
    }
}

// ---------------- kernel 4: edge epilogue (gather H1/H2 + elu + dot + sig) ---
__global__ __launch_bounds__(256) void edge_kernel(
        const float* __restrict__ ew1, const float* __restrict__ b1,
        const float* __restrict__ w2, const float* __restrict__ b2v,
        float* __restrict__ out, int out_size) {
    int wid = threadIdx.x >> 5, lane = threadIdx.x & 31;
    int p = blockIdx.x * 8 + wid;           // 0..31999
    int b = p / N_;
    int src = p % N_;
    float4 w1c = *(const float4*)&ew1[(size_t)512 * DFF + lane * 4];
    float4 b14 = *(const float4*)&b1[lane * 4];
    float4 w24 = *(const float4*)&w2[lane * 4];
    float b2s = b2v[0];
    float4 h1 = *(const float4*)&g_h12[(size_t)p * 256 + lane * 4];
    float bx = h1.x + b14.x, by = h1.y + b14.y;
    float bz = h1.z + b14.z, bw = h1.w + b14.w;
    size_t ebase = (size_t)p * KNN;
    #pragma unroll
    for (int i = 0; i < KNN; ++i) {
        int dst = g_dst[ebase + i];
        float val = g_val[ebase + i];
        float4 h2 = *(const float4*)&g_h12[((size_t)(b*N_ + dst)) * 256 + 128 + lane * 4];
        float x0 = bx + h2.x + val * w1c.x;
        float x1 = by + h2.y + val * w1c.y;
        float x2 = bz + h2.z + val * w1c.z;
        float x3 = bw + h2.w + val * w1c.w;
        x0 = x0 > 0.f ? x0 : expm1f(x0);
        x1 = x1 > 0.f ? x1 : expm1f(x1);
        x2 = x2 > 0.f ? x2 : expm1f(x2);
        x3 = x3 > 0.f ? x3 : expm1f(x3);
        float s = x0 * w24.x + x1 * w24.y + x2 * w24.z + x3 * w24.w;
        #pragma unroll
        for (int off = 16; off; off >>= 1) s += __shfl_down_sync(0xffffffffu, s, off);
        if (lane == 0) {
            int eid = (int)ebase + i;
            if (3*E_TOT + eid < out_size)
                out[3*E_TOT + eid] = 1.f / (1.f + expf(-(s + b2s)));
            if (eid*3 + 2 < out_size) {
                out[eid*3 + 0] = (float)b;
                out[eid*3 + 1] = (float)src;
                out[eid*3 + 2] = (float)dst;
            }
        }
    }
}

// -----------------------------------------------------------------------------
extern "C" void kernel_launch(void* const* d_in, const int* in_sizes, int n_in,
                              void* d_out, int out_size) {
    const float* inputs  = (const float*)d_in[0];
    const float* enc_w1  = (const float*)d_in[1];
    const float* enc_b1  = (const float*)d_in[2];
    const float* enc_w2  = (const float*)d_in[3];
    const float* enc_b2  = (const float*)d_in[4];
    const float* edge_w1 = (const float*)d_in[5];
    const float* edge_b1 = (const float*)d_in[6];
    const float* edge_w2 = (const float*)d_in[7];
    const float* edge_b2 = (const float*)d_in[8];
    const float* rot     = (const float*)d_in[9];
    float* out = (float*)d_out;

    // Fork/join: h12 depends ONLY on inputs — fork BEFORE enc.
    cudaStream_t s2 = 0;
    cudaEvent_t e1 = 0, e2 = 0;
    bool forked = (cudaStreamCreateWithFlags(&s2, cudaStreamNonBlocking) == cudaSuccess);
    if (forked && cudaEventCreateWithFlags(&e1, cudaEventDisableTiming) != cudaSuccess)
        forked = false;
    if (forked && cudaEventCreateWithFlags(&e2, cudaEventDisableTiming) != cudaSuccess)
        forked = false;

    size_t h12_smem = (size_t)(8192 + 16384) * sizeof(float);    // 96 KB
    cudaFuncSetAttribute(h12_kernel, cudaFuncAttributeMaxDynamicSharedMemorySize,
                         (int)h12_smem);
    if (forked) {
        cudaEventRecord(e1, 0);
        cudaStreamWaitEvent(s2, e1, 0);
        h12_kernel<<<(B_*N_)/128, 512, h12_smem, s2>>>(inputs, edge_w1);
        cudaEventRecord(e2, s2);
    }

    size_t enc_smem = (size_t)(4096 + 8192 + 8192) * sizeof(float);  // 80 KB
    cudaFuncSetAttribute(enc_kernel, cudaFuncAttributeMaxDynamicSharedMemorySize,
                         (int)enc_smem);
    enc_kernel<<<(B_*N_)/ENC_PTS, 256, enc_smem>>>(inputs, enc_w1, enc_b1,
                                                   enc_w2, enc_b2, rot);

    if (!forked)
        h12_kernel<<<(B_*N_)/128, 512, h12_smem>>>(inputs, edge_w1);

    sort_kernel<<<B_, 1024>>>(out, out_size);

    size_t tk_smem = (size_t)(2 * TKC * 128 + 2 * TKC) * sizeof(float)
                   + 256 * 8 * sizeof(unsigned long long);       // ~80.5 KB
    cudaFuncSetAttribute(topk_kernel, cudaFuncAttributeMaxDynamicSharedMemorySize,
                         (int)tk_smem);
    topk_kernel<<<192, 512, tk_smem>>>();

    if (forked) cudaStreamWaitEvent(0, e2, 0);
    edge_kernel<<<(B_*N_)/8, 256>>>(edge_w1, edge_b1, edge_w2, edge_b2,
                                    out, out_size);
}

// round 17
// speedup vs baseline: 1.2749x; 1.2749x over previous
#include <cuda_runtime.h>
#include <math.h>

#define B_    4
#define N_    8000
#define FIN   256
#define DD    128
#define DFF   128
#define NBINS 16
#define BINSZ 500
#define KNN   8
#define E_TOT (B_*N_*KNN)     /* 256000 */
#define ROTC  100             /* MAX_NUM_BINS/2, row stride of rot */

// ---------------- scratch (static device globals; no allocation) -------------
__device__ float g_pe[B_*N_*DD];          // encoded points
__device__ float g_norm[B_*N_];           // squared norms of encoded points
__device__ int   g_bin[B_*N_];            // LSH bin per point
__device__ int   g_perm[B_*N_];           // stable argsort by bin == bins_split
__device__ int   g_dst[E_TOT];            // per (b,src,slot) dst, dst-sorted
__device__ float g_val[E_TOT];            // matching kernel values
__device__ float g_h12[(size_t)B_*N_*256];// [point][0:128]=X*W1a, [128:256]=X*W1b

// ---------------- packed f32x2 helpers ---------------------------------------
#define FMA2(d, a, b) asm("fma.rn.f32x2 %0, %1, %2, %0;" : "+l"(d) : "l"(a), "l"(b))

__device__ __forceinline__ unsigned long long dup2(float v) {
    unsigned iv = __float_as_uint(v);
    unsigned long long r;
    asm("mov.b64 %0, {%1, %1};" : "=l"(r) : "r"(iv), "r"(iv));
    return r;
}
__device__ __forceinline__ float f2lo(unsigned long long u) {
    return __uint_as_float((unsigned)u);
}
__device__ __forceinline__ float f2hi(unsigned long long u) {
    return __uint_as_float((unsigned)(u >> 32));
}

// ---------------- cp.async helpers --------------------------------------------
#define CPA16(dst, src) asm volatile( \
    "cp.async.ca.shared.global [%0], [%1], 16;" :: "r"(dst), "l"(src))
#define CPA4(dst, src) asm volatile( \
    "cp.async.ca.shared.global [%0], [%1], 4;" :: "r"(dst), "l"(src))
#define CPACOMMIT() asm volatile("cp.async.commit_group;")
#define CPAWAIT0()  asm volatile("cp.async.wait_group 0;")

// +inf-keyed sentinel: sorts above every finite-d2 key; threshold bootstraps
// to +inf so the first KNN candidates always pass.
#define KEY_INIT 0x7F800000FFFFFFFFull

// ---------------- kernel 1: tiled encoder FFN + norms + LSH bin --------------
#define ENC_PTS 64
__global__ __launch_bounds__(256) void enc_kernel(
        const float* __restrict__ inputs,
        const float* __restrict__ w1, const float* __restrict__ b1,
        const float* __restrict__ w2, const float* __restrict__ b2,
        const float* __restrict__ rot) {
    extern __shared__ float sm[];
    float* xs = sm;                 // [64][64]
    float* ws = sm + 4096;          // [64][128]
    float* hs = sm + 12288;         // [64][128]
    __shared__ float b1s[DFF], b2s[DD];
    __shared__ float rots[DD * 8];
    __shared__ float ms[ENC_PTS][8];
    int tid = threadIdx.x;
    int wid = tid >> 5, tx = tid & 31;
    int n0 = blockIdx.x * ENC_PTS;

    if (tid < DFF) b1s[tid] = b1[tid];
    else b2s[tid - DFF] = b2[tid - DFF];
    for (int t = tid; t < DD * 8; t += 256) {
        int d = t >> 3, j = t & 7;
        rots[t] = rot[d * ROTC + j];
    }

    unsigned long long acc[8][2];
    #pragma unroll
    for (int rr = 0; rr < 8; ++rr) { acc[rr][0] = 0ull; acc[rr][1] = 0ull; }

    for (int kc = 0; kc < FIN; kc += 64) {
        __syncthreads();
        for (int t = tid; t < 1024; t += 256) {
            int p = t >> 4, k4 = t & 15;
            ((float4*)xs)[p * 16 + k4] =
                ((const float4*)(inputs + (size_t)(n0 + p) * FIN + kc))[k4];
        }
        for (int t = tid; t < 2048; t += 256) {
            int k = t >> 5, c4 = t & 31;
            ((float4*)ws)[k * 32 + c4] =
                ((const float4*)(w1 + (size_t)(kc + k) * DFF))[c4];
        }
        __syncthreads();
        for (int k4 = 0; k4 < 64; k4 += 4) {
            float4 e4[8];
            #pragma unroll
            for (int rr = 0; rr < 8; ++rr)
                e4[rr] = *(const float4*)&xs[(wid * 8 + rr) * 64 + k4];
            #pragma unroll
            for (int j = 0; j < 4; ++j) {
                ulonglong2 wp = *(const ulonglong2*)&ws[(k4 + j) * DFF + tx * 4];
                #pragma unroll
                for (int rr = 0; rr < 8; ++rr) {
                    float ev = (j == 0) ? e4[rr].x : (j == 1) ? e4[rr].y
                             : (j == 2) ? e4[rr].z : e4[rr].w;
                    unsigned long long ed = dup2(ev);
                    FMA2(acc[rr][0], ed, wp.x);
                    FMA2(acc[rr][1], ed, wp.y);
                }
            }
        }
    }
    #pragma unroll
    for (int rr = 0; rr < 8; ++rr) {
        int p = wid * 8 + rr;
        float h0 = f2lo(acc[rr][0]) + b1s[tx * 4 + 0];
        float h1 = f2hi(acc[rr][0]) + b1s[tx * 4 + 1];
        float h2 = f2lo(acc[rr][1]) + b1s[tx * 4 + 2];
        float h3 = f2hi(acc[rr][1]) + b1s[tx * 4 + 3];
        h0 = h0 > 0.f ? h0 : expm1f(h0);
        h1 = h1 > 0.f ? h1 : expm1f(h1);
        h2 = h2 > 0.f ? h2 : expm1f(h2);
        h3 = h3 > 0.f ? h3 : expm1f(h3);
        *(float4*)&hs[p * DFF + tx * 4] = make_float4(h0, h1, h2, h3);
    }

    #pragma unroll
    for (int rr = 0; rr < 8; ++rr) { acc[rr][0] = 0ull; acc[rr][1] = 0ull; }
    for (int half = 0; half < 2; ++half) {
        __syncthreads();
        for (int t = tid; t < 2048; t += 256) {
            int k = t >> 5, c4 = t & 31;
            ((float4*)ws)[k * 32 + c4] =
                ((const float4*)(w2 + (size_t)(half * 64 + k) * DD))[c4];
        }
        __syncthreads();
        for (int k4 = 0; k4 < 64; k4 += 4) {
            float4 e4[8];
            #pragma unroll
            for (int rr = 0; rr < 8; ++rr)
                e4[rr] = *(const float4*)&hs[(wid * 8 + rr) * DFF + half * 64 + k4];
            #pragma unroll
            for (int j = 0; j < 4; ++j) {
                ulonglong2 wp = *(const ulonglong2*)&ws[(k4 + j) * DD + tx * 4];
                #pragma unroll
                for (int rr = 0; rr < 8; ++rr) {
                    float ev = (j == 0) ? e4[rr].x : (j == 1) ? e4[rr].y
                             : (j == 2) ? e4[rr].z : e4[rr].w;
                    unsigned long long ed = dup2(ev);
                    FMA2(acc[rr][0], ed, wp.x);
                    FMA2(acc[rr][1], ed, wp.y);
                }
            }
        }
    }
    __syncthreads();
    #pragma unroll
    for (int rr = 0; rr < 8; ++rr) {
        int p = wid * 8 + rr;
        int n = n0 + p;
        float o0 = f2lo(acc[rr][0]) + b2s[tx * 4 + 0];
        float o1 = f2hi(acc[rr][0]) + b2s[tx * 4 + 1];
        float o2 = f2lo(acc[rr][1]) + b2s[tx * 4 + 2];
        float o3 = f2hi(acc[rr][1]) + b2s[tx * 4 + 3];
        float4 ov = make_float4(o0, o1, o2, o3);
        *(float4*)&hs[p * DD + tx * 4] = ov;
        *(float4*)&g_pe[(size_t)n * DD + tx * 4] = ov;
        float pn = o0 * o0 + o1 * o1 + o2 * o2 + o3 * o3;
        #pragma unroll
        for (int off = 16; off; off >>= 1)
            pn += __shfl_xor_sync(0xffffffffu, pn, off);
        if (tx == 0) g_norm[n] = pn;
    }
    __syncthreads();

    for (int t = tid; t < ENC_PTS * 8; t += 256) {
        int p = t >> 3, j = t & 7;
        float m = 0.f;
        #pragma unroll 8
        for (int d = 0; d < DD; ++d) m += hs[p * DD + d] * rots[d * 8 + j];
        ms[p][j] = m;
    }
    __syncthreads();
    if (tid < ENC_PTS) {
        float best = ms[tid][0]; int bi = 0;
        #pragma unroll
        for (int j = 1; j < NBINS; ++j) {
            float v = (j < 8) ? ms[tid][j] : -ms[tid][j - 8];
            if (v > best) { best = v; bi = j; }
        }
        g_bin[n0 + tid] = bi;
    }
}

// ---------------- kernel 1b: H12 = X @ [W1a | W1b] (edge-FFN precompute) -----
__global__ __launch_bounds__(512) void h12_kernel(
        const float* __restrict__ inputs, const float* __restrict__ ew1) {
    extern __shared__ float sm[];
    float* xs = sm;                 // [128][64]
    float* ws = sm + 8192;          // [64][256]
    int tid = threadIdx.x;
    int wid = tid >> 5, tx = tid & 31;
    int n0 = blockIdx.x * 128;

    unsigned long long acc[8][4];
    #pragma unroll
    for (int rr = 0; rr < 8; ++rr)
        acc[rr][0] = acc[rr][1] = acc[rr][2] = acc[rr][3] = 0ull;

    for (int kc = 0; kc < FIN; kc += 64) {
        __syncthreads();
        for (int t = tid; t < 2048; t += 512) {
            int p = t >> 4, k4 = t & 15;
            ((float4*)xs)[p * 16 + k4] =
                ((const float4*)(inputs + (size_t)(n0 + p) * FIN + kc))[k4];
        }
        for (int t = tid; t < 4096; t += 512) {
            int k = t >> 6, j4 = t & 63;
            const float* srcp = (j4 < 32)
                ? (ew1 + (size_t)(kc + k) * DFF + j4 * 4)
                : (ew1 + (size_t)(256 + kc + k) * DFF + (j4 - 32) * 4);
            ((float4*)ws)[k * 64 + j4] = *(const float4*)srcp;
        }
        __syncthreads();
        for (int k4 = 0; k4 < 64; k4 += 4) {
            float4 e4[8];
            #pragma unroll
            for (int rr = 0; rr < 8; ++rr)
                e4[rr] = *(const float4*)&xs[(wid * 8 + rr) * 64 + k4];
            #pragma unroll
            for (int j = 0; j < 4; ++j) {
                ulonglong2 wa = *(const ulonglong2*)&ws[(k4 + j) * 256 + tx * 4];
                ulonglong2 wb = *(const ulonglong2*)&ws[(k4 + j) * 256 + 128 + tx * 4];
                #pragma unroll
                for (int rr = 0; rr < 8; ++rr) {
                    float ev = (j == 0) ? e4[rr].x : (j == 1) ? e4[rr].y
                             : (j == 2) ? e4[rr].z : e4[rr].w;
                    unsigned long long ed = dup2(ev);
                    FMA2(acc[rr][0], ed, wa.x);
                    FMA2(acc[rr][1], ed, wa.y);
                    FMA2(acc[rr][2], ed, wb.x);
                    FMA2(acc[rr][3], ed, wb.y);
                }
            }
        }
    }
    #pragma unroll
    for (int rr = 0; rr < 8; ++rr) {
        size_t n = (size_t)(n0 + wid * 8 + rr);
        *(float4*)&g_h12[n * 256 + tx * 4] =
            make_float4(f2lo(acc[rr][0]), f2hi(acc[rr][0]),
                        f2lo(acc[rr][1]), f2hi(acc[rr][1]));
        *(float4*)&g_h12[n * 256 + 128 + tx * 4] =
            make_float4(f2lo(acc[rr][2]), f2hi(acc[rr][2]),
                        f2lo(acc[rr][3]), f2hi(acc[rr][3]));
    }
}

// ---------------- kernel 2: stable counting sort, 1024 threads ---------------
__global__ __launch_bounds__(1024) void sort_kernel(float* __restrict__ out,
                                                    int out_size) {
    int b = blockIdx.x;
    __shared__ int bins[N_];
    __shared__ int cnt[NBINS];
    __shared__ int basebin[NBINS];
    __shared__ int wcnt[32][NBINS];
    int tid = threadIdx.x, wid = tid >> 5, lane = tid & 31;
    unsigned ltmask = (1u << lane) - 1u;
    for (int i = tid; i < N_; i += 1024) bins[i] = g_bin[b*N_ + i];
    if (tid < NBINS) cnt[tid] = 0;
    __syncthreads();
    for (int i = tid; i < N_; i += 1024) {
        int bi = bins[i];
        unsigned m = __match_any_sync(0xffffffffu, bi);
        if ((m & ltmask) == 0) atomicAdd(&cnt[bi], __popc(m));
    }
    __syncthreads();
    if (tid == 0) {
        int s = 0;
        for (int k = 0; k < NBINS; ++k) { basebin[k] = s; s += cnt[k]; }
    }
    __syncthreads();
    for (int c0 = 0; c0 < N_; c0 += 1024) {
        int i = c0 + tid;
        int bi = (i < N_) ? bins[i] : -1;
        unsigned m = __match_any_sync(0xffffffffu, bi);
        int wrank = __popc(m & ltmask);
        if (tid < 512) wcnt[tid >> 4][tid & 15] = 0;
        __syncthreads();
        if ((m & ltmask) == 0 && bi >= 0) wcnt[wid][bi] = __popc(m);
        __syncthreads();
        if (bi >= 0) {
            int off = basebin[bi];
            for (int w = 0; w < wid; ++w) off += wcnt[w][bi];
            g_perm[b*N_ + off + wrank] = i;
        }
        __syncthreads();
        if (tid < NBINS) {
            int t = 0;
            #pragma unroll
            for (int w = 0; w < 32; ++w) t += wcnt[w][tid];
            basebin[tid] += t;
        }
        __syncthreads();
    }
    for (int i = tid; i < N_; i += 1024) {
        int idx = 4*E_TOT + b*N_ + i;
        if (idx < out_size) out[idx] = (float)g_perm[b*N_ + i];
    }
}

// ---------------- kernel 3: top-8 by min d2 (best config: R13/R15) -----------
// 256 blocks = 64 (b,bin) x 4 row slabs of 128. 8-lane groups, 4 rows/group in
// registers. 4 cols per iter; 4-col transposed butterfly reduce (4 shuffles/row)
// lands col (l8&3) on lanes 0..3. Thresholds in registers; rare inserts
// turn-serialized into smem u64 keys (exact (d2,idx) tie-break).
#define TKC 64
__global__ __launch_bounds__(256, 2) void topk_kernel() {
    int bb = blockIdx.x;
    int rg = bb & 3;
    int bbin = bb >> 2;
    int b = bbin / NBINS, bin = bbin % NBINS;
    extern __shared__ float smx[];
    float4* colbuf4 = (float4*)smx;                        // [2][64][32] f4 64KB
    float* cns = smx + 2 * TKC * 128;                      // [2][64]
    unsigned long long* keys =
        (unsigned long long*)(smx + 2 * TKC * 128 + 2 * TKC);  // [128][8] 8KB
    unsigned smem_u = (unsigned)__cvta_generic_to_shared(smx);
    unsigned cb_u   = smem_u;
    unsigned cn_u   = smem_u + 2 * TKC * 128 * 4;

    const int* perm = g_perm + b*N_ + bin*BINSZ;
    const float* pe = g_pe + (size_t)b*N_*DD;
    const float* nrm = g_norm + b*N_;
    int tid = threadIdx.x;
    int grp = tid >> 3, l8 = tid & 7;                      // 32 groups x 8 lanes
    int rbase = rg * 128;

    unsigned rvm = 0;
    float rn[4];
    ulonglong2 rp[4][4];                                   // 4 rows x 16 floats
    #pragma unroll
    for (int r = 0; r < 4; ++r) {
        int row = rbase + grp + 32*r;
        if (row < BINSZ) rvm |= 1u << r;
        int rowc = (row < BINSZ) ? row : 0;
        int rs = perm[rowc];
        rn[r] = nrm[rs];
        const ulonglong2* prow = (const ulonglong2*)(pe + (size_t)rs*DD);
        #pragma unroll
        for (int ch = 0; ch < 4; ++ch) rp[r][ch] = prow[l8 + 8*ch];
    }
    for (int t = tid; t < 128*8; t += 256) keys[t] = KEY_INIT;
    float thr[4];
    #pragma unroll
    for (int r = 0; r < 4; ++r) thr[r] = __uint_as_float(0x7F800000u); // +inf

    const int NT = (BINSZ + TKC - 1) / TKC;                // 8 tiles
    {
        for (int t = tid; t < TKC*32; t += 256) {
            int c = t >> 5, k = t & 31;
            CPA16(cb_u + (unsigned)t * 16,
                  (const void*)(pe + (size_t)perm[c]*DD + k*4));
        }
        if (tid < TKC) CPA4(cn_u + tid*4, (const void*)(nrm + perm[tid]));
        CPACOMMIT();
    }
    CPAWAIT0();
    __syncthreads();

    int lc = l8 & 3;                                       // lane's col slot
    for (int tIdx = 0; tIdx < NT; ++tIdx) {
        int bf = tIdx & 1;
        int cc = tIdx * TKC;
        int csize = min(TKC, BINSZ - cc);                  // 64 or 52 (div by 4)
        if (tIdx + 1 < NT) {
            int ncc = cc + TKC;
            int ncs = min(TKC, BINSZ - ncc);
            unsigned cbn = cb_u + (unsigned)(bf ^ 1) * TKC * 128 * 4;
            for (int t = tid; t < ncs*32; t += 256) {
                int c = t >> 5, k = t & 31;
                CPA16(cbn + (unsigned)t * 16,
                      (const void*)(pe + (size_t)perm[ncc + c]*DD + k*4));
            }
            if (tid < ncs) CPA4(cn_u + ((bf ^ 1) * TKC + tid) * 4,
                                (const void*)(nrm + perm[ncc + tid]));
            CPACOMMIT();
        }
        const float4* cb = colbuf4 + bf * TKC * 32;
        const float* cnorm = cns + bf * TKC;
        for (int c = 0; c < csize; c += 4) {
            unsigned long long acc[4][4];                  // [row][col]
            #pragma unroll
            for (int r = 0; r < 4; ++r)
                #pragma unroll
                for (int j = 0; j < 4; ++j) acc[r][j] = 0ull;
            const ulonglong2* col0 = (const ulonglong2*)&cb[(c+0)*32];
            const ulonglong2* col1 = (const ulonglong2*)&cb[(c+1)*32];
            const ulonglong2* col2 = (const ulonglong2*)&cb[(c+2)*32];
            const ulonglong2* col3 = (const ulonglong2*)&cb[(c+3)*32];
            #pragma unroll
            for (int ch = 0; ch < 4; ++ch) {
                ulonglong2 cv0 = col0[l8 + 8*ch];
                ulonglong2 cv1 = col1[l8 + 8*ch];
                ulonglong2 cv2 = col2[l8 + 8*ch];
                ulonglong2 cv3 = col3[l8 + 8*ch];
                #pragma unroll
                for (int r = 0; r < 4; ++r) {
                    FMA2(acc[r][0], rp[r][ch].x, cv0.x);
                    FMA2(acc[r][0], rp[r][ch].y, cv0.y);
                    FMA2(acc[r][1], rp[r][ch].x, cv1.x);
                    FMA2(acc[r][1], rp[r][ch].y, cv1.y);
                    FMA2(acc[r][2], rp[r][ch].x, cv2.x);
                    FMA2(acc[r][2], rp[r][ch].y, cv2.y);
                    FMA2(acc[r][3], rp[r][ch].x, cv3.x);
                    FMA2(acc[r][3], rp[r][ch].y, cv3.y);
                }
            }
            float cn = cnorm[c + lc];
            float d2v[4];
            unsigned passm = 0;
            #pragma unroll
            for (int r = 0; r < 4; ++r) {
                float p0 = f2lo(acc[r][0]) + f2hi(acc[r][0]);
                float p1 = f2lo(acc[r][1]) + f2hi(acc[r][1]);
                float p2 = f2lo(acc[r][2]) + f2hi(acc[r][2]);
                float p3 = f2lo(acc[r][3]) + f2hi(acc[r][3]);
                float vA = (l8 & 1) ? p0 : p1;
                float qA = __shfl_xor_sync(0xffffffffu, vA, 1, 8);
                float s01 = ((l8 & 1) ? p1 : p0) + qA;
                float vB = (l8 & 1) ? p2 : p3;
                float qB = __shfl_xor_sync(0xffffffffu, vB, 1, 8);
                float s23 = ((l8 & 1) ? p3 : p2) + qB;
                float vC = (l8 & 2) ? s01 : s23;
                float qC = __shfl_xor_sync(0xffffffffu, vC, 2, 8);
                float a = ((l8 & 2) ? s23 : s01) + qC;
                a += __shfl_xor_sync(0xffffffffu, a, 4, 8);
                float d2 = fmaxf((rn[r] - 2.0f * a) + cn, 1e-6f);
                d2v[r] = d2;
                if (((rvm >> r) & 1u) && l8 < 4 && d2 <= thr[r])
                    passm |= 1u << r;
            }
            if (__ballot_sync(0xffffffffu, passm)) {
                #pragma unroll
                for (int t = 0; t < 4; ++t) {
                    if (l8 == t && passm) {
                        #pragma unroll
                        for (int r = 0; r < 4; ++r) {
                            if ((passm >> r) & 1u) {
                                unsigned long long* kr = &keys[(r*32 + grp)*8];
                                unsigned long long key =
                                    ((unsigned long long)
                                     __float_as_uint(d2v[r]) << 32)
                                    | (unsigned)(cc + c + t);
                                if (key < kr[7]) {
                                    kr[7] = key;
                                    #pragma unroll
                                    for (int s = 7; s > 0; --s) {
                                        if (kr[s] < kr[s-1]) {
                                            unsigned long long tm = kr[s];
                                            kr[s] = kr[s-1]; kr[s-1] = tm;
                                        } else break;
                                    }
                                }
                            }
                        }
                    }
                    __syncwarp();
                }
                #pragma unroll
                for (int r = 0; r < 4; ++r)
                    thr[r] = __uint_as_float(
                        (unsigned)(keys[(r*32 + grp)*8 + 7] >> 32));
            }
        }
        CPAWAIT0();
        __syncthreads();
    }
    // ---- writeback: one thread per row ----
    if (tid < 128) {
        int grow = rbase + tid;
        if (grow < BINSZ) {
            int rsrc = perm[grow];
            unsigned long long* kr = &keys[tid * 8];
            int dsts[KNN]; float vals[KNN];
            #pragma unroll
            for (int s = 0; s < KNN; ++s) {
                unsigned long long k = kr[s];
                float d2 = __uint_as_float((unsigned)(k >> 32));
                dsts[s] = perm[(unsigned)k];
                vals[s] = expf(-0.1f * sqrtf(d2));
            }
            #pragma unroll
            for (int i = 1; i < KNN; ++i) {
                int dk = dsts[i]; float vk = vals[i]; int j = i - 1;
                while (j >= 0 && dsts[j] > dk) {
                    dsts[j+1] = dsts[j]; vals[j+1] = vals[j]; --j;
                }
                dsts[j+1] = dk; vals[j+1] = vk;
            }
            size_t base = ((size_t)b*N_ + rsrc) * KNN;
            #pragma unroll
            for (int s = 0; s < KNN; ++s) {
                g_dst[base+s] = dsts[s]; g_val[base+s] = vals[s];
            }
        }
    }
}

// ---------------- kernel 4: edge epilogue (gather H1/H2 + elu + dot + sig) ---
__global__ __launch_bounds__(256) void edge_kernel(
        const float* __restrict__ ew1, const float* __restrict__ b1,
        const float* __restrict__ w2, const float* __restrict__ b2v,
        float* __restrict__ out, int out_size) {
    int wid = threadIdx.x >> 5, lane = threadIdx.x & 31;
    int p = blockIdx.x * 8 + wid;           // 0..31999
    int b = p / N_;
    int src = p % N_;
    float4 w1c = *(const float4*)&ew1[(size_t)512 * DFF + lane * 4];
    float4 b14 = *(const float4*)&b1[lane * 4];
    float4 w24 = *(const float4*)&w2[lane * 4];
    float b2s = b2v[0];
    float4 h1 = *(const float4*)&g_h12[(size_t)p * 256 + lane * 4];
    float bx = h1.x + b14.x, by = h1.y + b14.y;
    float bz = h1.z + b14.z, bw = h1.w + b14.w;
    size_t ebase = (size_t)p * KNN;
    #pragma unroll
    for (int i = 0; i < KNN; ++i) {
        int dst = g_dst[ebase + i];
        float val = g_val[ebase + i];
        float4 h2 = *(const float4*)&g_h12[((size_t)(b*N_ + dst)) * 256 + 128 + lane * 4];
        float x0 = bx + h2.x + val * w1c.x;
        float x1 = by + h2.y + val * w1c.y;
        float x2 = bz + h2.z + val * w1c.z;
        float x3 = bw + h2.w + val * w1c.w;
        x0 = x0 > 0.f ? x0 : expm1f(x0);
        x1 = x1 > 0.f ? x1 : expm1f(x1);
        x2 = x2 > 0.f ? x2 : expm1f(x2);
        x3 = x3 > 0.f ? x3 : expm1f(x3);
        float s = x0 * w24.x + x1 * w24.y + x2 * w24.z + x3 * w24.w;
        #pragma unroll
        for (int off = 16; off; off >>= 1) s += __shfl_down_sync(0xffffffffu, s, off);
        if (lane == 0) {
            int eid = (int)ebase + i;
            if (3*E_TOT + eid < out_size)
                out[3*E_TOT + eid] = 1.f / (1.f + expf(-(s + b2s)));
            if (eid*3 + 2 < out_size) {
                out[eid*3 + 0] = (float)b;
                out[eid*3 + 1] = (float)src;
                out[eid*3 + 2] = (float)dst;
            }
        }
    }
}

// -----------------------------------------------------------------------------
extern "C" void kernel_launch(void* const* d_in, const int* in_sizes, int n_in,
                              void* d_out, int out_size) {
    const float* inputs  = (const float*)d_in[0];
    const float* enc_w1  = (const float*)d_in[1];
    const float* enc_b1  = (const float*)d_in[2];
    const float* enc_w2  = (const float*)d_in[3];
    const float* enc_b2  = (const float*)d_in[4];
    const float* edge_w1 = (const float*)d_in[5];
    const float* edge_b1 = (const float*)d_in[6];
    const float* edge_w2 = (const float*)d_in[7];
    const float* edge_b2 = (const float*)d_in[8];
    const float* rot     = (const float*)d_in[9];
    float* out = (float*)d_out;

    // Fork/join: h12 depends ONLY on inputs — fork BEFORE enc so it runs
    // concurrently with enc + sort + topk, finishing well before edge.
    cudaStream_t s2 = 0;
    cudaEvent_t e1 = 0, e2 = 0;
    bool forked = (cudaStreamCreateWithFlags(&s2, cudaStreamNonBlocking) == cudaSuccess);
    if (forked && cudaEventCreateWithFlags(&e1, cudaEventDisableTiming) != cudaSuccess)
        forked = false;
    if (forked && cudaEventCreateWithFlags(&e2, cudaEventDisableTiming) != cudaSuccess)
        forked = false;

    size_t h12_smem = (size_t)(8192 + 16384) * sizeof(float);    // 96 KB
    cudaFuncSetAttribute(h12_kernel, cudaFuncAttributeMaxDynamicSharedMemorySize,
                         (int)h12_smem);
    if (forked) {
        cudaEventRecord(e1, 0);                 // fork point: nothing queued yet
        cudaStreamWaitEvent(s2, e1, 0);
        h12_kernel<<<(B_*N_)/128, 512, h12_smem, s2>>>(inputs, edge_w1);
        cudaEventRecord(e2, s2);
    }

    size_t enc_smem = (size_t)(4096 + 8192 + 8192) * sizeof(float);  // 80 KB
    cudaFuncSetAttribute(enc_kernel, cudaFuncAttributeMaxDynamicSharedMemorySize,
                         (int)enc_smem);
    enc_kernel<<<(B_*N_)/ENC_PTS, 256, enc_smem>>>(inputs, enc_w1, enc_b1,
                                                   enc_w2, enc_b2, rot);

    if (!forked)
        h12_kernel<<<(B_*N_)/128, 512, h12_smem>>>(inputs, edge_w1);

    sort_kernel<<<B_, 1024>>>(out, out_size);

    size_t tk_smem = (size_t)(2 * TKC * 128 + 2 * TKC) * sizeof(float)
                   + 128 * 8 * sizeof(unsigned long long);       // ~73 KB
    cudaFuncSetAttribute(topk_kernel, cudaFuncAttributeMaxDynamicSharedMemorySize,
                         (int)tk_smem);
    topk_kernel<<<B_*NBINS*4, 256, tk_smem>>>();

    if (forked) cudaStreamWaitEvent(0, e2, 0);
    edge_kernel<<<(B_*N_)/8, 256>>>(edge_w1, edge_b1, edge_w2, edge_b2,
                                    out, out_size);
}